// round 8
// baseline (speedup 1.0000x reference)
#include <cuda_runtime.h>
#include <math.h>

#define Bn 32
#define Rr 13
#define Cc 13
#define Aa 5
#define Kk 20
#define CELL 25
#define Nn 845                       // R*C*A
#define TOTAL (Bn * Nn)              // 27040
#define THRESH 0.5f
#define NMS_TH 0.4f
#define TPB 192
#define NBLK ((TOTAL + TPB - 1) / TPB)   // 141
#define NBK (Bn * Kk)                // 640
#define CAP Nn
#define SUPW ((CAP + 31) / 32)       // 27

// Static device scratch (no allocations allowed).
__device__ float        g_cs[NBK * CAP];   // candidate scores
__device__ int          g_cn[NBK * CAP];   // candidate box index n
__device__ float4       g_cb[NBK * CAP];   // candidate boxes (x1,y1,x2,y2)
__device__ int          g_cnt[NBK];        // per-(b,k) candidate counts (reset by NMS tail)
__device__ unsigned int g_done;            // done-block counter   (reset by last block)

__device__ __forceinline__ float sigmoid_(float v) {
    return 1.0f / (1.0f + __expf(-v));
}

__global__ void __launch_bounds__(TPB)
region_fused(const float* __restrict__ x,
             const float* __restrict__ bias,
             float* __restrict__ out) {
    const int tid = threadIdx.x;
    const int gid = blockIdx.x * TPB + tid;

    __shared__ int      s_cnt;
    __shared__ int      s_gid[TPB];
    __shared__ float    s_obj[TPB];
    __shared__ float4   s_box[TPB];
    __shared__ unsigned s_done;

    if (tid == 0) s_cnt = 0;
    __syncthreads();

    // ---- Phase 1: decode box/obj for every cell, write zeros for class slots,
    //      compact cells with obj > 0.5 (necessary for any class to pass).
    if (gid < TOTAL) {
        const float* t = x + (size_t)gid * CELL;
        int n    = gid % Nn;
        int a    = n % Aa;
        int cell = n / Aa;
        int col  = cell % Cc;
        int row  = cell / Cc;

        float bx  = (sigmoid_(t[0]) + (float)col) * (1.0f / (float)Cc);
        float by  = (sigmoid_(t[1]) + (float)row) * (1.0f / (float)Rr);
        float bw  = __expf(t[2]) * bias[2 * a]     * (1.0f / (float)Rr);
        float bh  = __expf(t[3]) * bias[2 * a + 1] * (1.0f / (float)Cc);
        float obj = sigmoid_(t[4]);

        float* o = out + (size_t)gid * CELL;
        o[0] = bx; o[1] = by; o[2] = bw; o[3] = bh; o[4] = obj;
        #pragma unroll
        for (int j = 0; j < Kk; j++) o[5 + j] = 0.0f;

        if (obj > THRESH) {
            int p = atomicAdd(&s_cnt, 1);
            s_gid[p] = gid;
            s_obj[p] = obj;
            float x1 = bx - 0.5f * bw;
            float y1 = by - 0.5f * bh;
            s_box[p] = make_float4(x1, y1, x1 + bw, y1 + bh);
        }
    }
    __syncthreads();

    // ---- Phase 2: dense softmax over compacted cells; push rare candidates.
    const int cnt = s_cnt;
    for (int i = tid; i < cnt; i += TPB) {
        int g2    = s_gid[i];
        float obj = s_obj[i];
        const float* t = x + (size_t)g2 * CELL + 5;

        float e[Kk];
        float s = 0.0f;
        #pragma unroll
        for (int j = 0; j < Kk; j++) { e[j] = __expf(t[j]); s += e[j]; }
        float inv = 1.0f / s;

        int b2 = g2 / Nn;
        int n2 = g2 % Nn;
        #pragma unroll
        for (int j = 0; j < Kk; j++) {
            float p = obj * e[j] * inv;
            if (p > THRESH) {
                out[(size_t)g2 * CELL + 5 + j] = p;
                int slot = b2 * Kk + j;
                int q = atomicAdd(&g_cnt[slot], 1);
                g_cs[slot * CAP + q] = p;
                g_cn[slot * CAP + q] = n2;
                g_cb[slot * CAP + q] = s_box[i];
            }
        }
    }

    // ---- Done-barrier: last finishing block runs the (tiny) NMS tail.
    __threadfence();
    __syncthreads();
    if (tid == 0) s_done = atomicAdd(&g_done, 1u);
    __syncthreads();
    if (s_done != (unsigned)(NBLK - 1)) return;

    if (tid == 0) g_done = 0;   // reset for next graph replay
    __threadfence();

    // ---- Phase 3 (last block only): greedy NMS per (b,k) over compacted lists.
    for (int t = tid; t < NBK; t += TPB) {
        int V = g_cnt[t];
        g_cnt[t] = 0;           // reset for next replay
        if (V <= 1) continue;

        int b = t / Kk;
        int k = t % Kk;
        const float*  cs = g_cs + (size_t)t * CAP;
        const int*    cn = g_cn + (size_t)t * CAP;
        const float4* cb = g_cb + (size_t)t * CAP;

        unsigned sup[SUPW], used[SUPW];
        int nw = (V + 31) >> 5;
        for (int w = 0; w < nw; w++) { sup[w] = 0u; used[w] = 0u; }

        // Selection-based greedy: process in (score desc, index asc) order.
        for (int it = 0; it < V; it++) {
            int   best = -1, bn = 0x7fffffff;
            float bs = -1.0f;
            for (int j = 0; j < V; j++) {
                if ((used[j >> 5] >> (j & 31)) & 1u) continue;
                float sj = cs[j];
                int   nj = cn[j];
                if (sj > bs || (sj == bs && nj < bn)) { best = j; bs = sj; bn = nj; }
            }
            used[best >> 5] |= 1u << (best & 31);
            if ((sup[best >> 5] >> (best & 31)) & 1u) continue;  // not alive

            float4 bb = cb[best];
            float  ab = (bb.z - bb.x) * (bb.w - bb.y);
            for (int j = 0; j < V; j++) {
                if ((used[j >> 5] >> (j & 31)) & 1u) continue;
                if ((sup[j >> 5]  >> (j & 31)) & 1u) continue;
                float4 cj = cb[j];
                float iw = fminf(bb.z, cj.z) - fmaxf(bb.x, cj.x);
                float ih = fminf(bb.w, cj.w) - fmaxf(bb.y, cj.y);
                iw = fmaxf(iw, 0.0f);
                ih = fmaxf(ih, 0.0f);
                float inter = iw * ih;
                float aj    = (cj.z - cj.x) * (cj.w - cj.y);
                float uni   = fmaxf(ab + aj - inter, 1e-9f);
                if (inter / uni > NMS_TH) sup[j >> 5] |= 1u << (j & 31);
            }
        }
        for (int j = 0; j < V; j++) {
            if ((sup[j >> 5] >> (j & 31)) & 1u)
                out[((size_t)(b * Nn + cn[j])) * CELL + 5 + k] = 0.0f;
        }
    }
}

extern "C" void kernel_launch(void* const* d_in, const int* in_sizes, int n_in,
                              void* d_out, int out_size) {
    const float* x    = (const float*)d_in[0];
    const float* bias = (const float*)d_in[1];
    float* out        = (float*)d_out;
    region_fused<<<NBLK, TPB>>>(x, bias, out);
}

// round 9
// speedup vs baseline: 1.2149x; 1.2149x over previous
#include <cuda_runtime.h>
#include <math.h>

#define Bn 32
#define Rr 13
#define Cc 13
#define Aa 5
#define Kk 20
#define CELL 25
#define Nn 845                        // R*C*A
#define TOTAL (Bn * Nn)               // 27040
#define THRESH 0.5f
#define NMS_TH 0.4f
#define TPB 256
#define NBLK ((TOTAL + TPB - 1) / TPB)    // 106 (last block: 160 cells)
#define NBK (Bn * Kk)                 // 640
#define CAP Nn
#define SUPW ((CAP + 31) / 32)

// Static device scratch (no allocations allowed).
__device__ float        g_cs[NBK * CAP];   // candidate scores
__device__ int          g_cn[NBK * CAP];   // candidate box index n
__device__ float4       g_cb[NBK * CAP];   // candidate boxes (x1,y1,x2,y2)
__device__ int          g_cnt[NBK];        // per-(b,k) counts (reset by tail)
__device__ unsigned int g_done;            // done-block counter (reset by last block)

__device__ __forceinline__ float sigmoid_(float v) {
    return 1.0f / (1.0f + __expf(-v));
}

__global__ void __launch_bounds__(TPB)
region_fused(const float* __restrict__ x,
             const float* __restrict__ bias,
             float* __restrict__ out) {
    const int tid = threadIdx.x;
    const int blockBase = blockIdx.x * TPB;          // first cell of this block
    const int cells = min(TPB, TOTAL - blockBase);   // 256 or 160

    __shared__ float    s_data[TPB * CELL];          // 25.6 KB, in-place transform
    __shared__ unsigned s_done;

    // ---- Coalesced vectorized load: block's cells are contiguous (cells*100 B,
    //      16B-aligned since blockBase*100 is a multiple of 25600).
    {
        const float4* src = (const float4*)(x + (size_t)blockBase * CELL);
        float4* dst = (float4*)s_data;
        int n4 = cells * CELL / 4;                   // 1600 or 1000
        for (int i = tid; i < n4; i += TPB) dst[i] = src[i];
        // cells*25 is divisible by 4? 256*25=6400 ✓, 160*25=4000 ✓
    }
    __syncthreads();

    // ---- Decode + inline softmax, transforming the cell in place in shared.
    if (tid < cells) {
        float* t = s_data + tid * CELL;              // stride 25: bank-conflict-free
        const int gid = blockBase + tid;
        int n    = gid % Nn;
        int a    = n % Aa;
        int cell = n / Aa;
        int col  = cell % Cc;
        int row  = cell / Cc;

        float bx  = (sigmoid_(t[0]) + (float)col) * (1.0f / (float)Cc);
        float by  = (sigmoid_(t[1]) + (float)row) * (1.0f / (float)Rr);
        float bw  = __expf(t[2]) * __ldg(&bias[2 * a])     * (1.0f / (float)Rr);
        float bh  = __expf(t[3]) * __ldg(&bias[2 * a + 1]) * (1.0f / (float)Cc);
        float obj = sigmoid_(t[4]);

        t[0] = bx; t[1] = by; t[2] = bw; t[3] = bh; t[4] = obj;

        if (obj > THRESH) {
            float e[Kk];
            float s = 0.0f;
            #pragma unroll
            for (int j = 0; j < Kk; j++) { e[j] = __expf(t[5 + j]); s += e[j]; }
            float inv = 1.0f / s;

            float x1 = bx - 0.5f * bw;
            float y1 = by - 0.5f * bh;
            float4 box = make_float4(x1, y1, x1 + bw, y1 + bh);
            int b2 = gid / Nn;

            #pragma unroll
            for (int j = 0; j < Kk; j++) {
                float p = obj * e[j] * inv;
                if (p > THRESH) {
                    t[5 + j] = p;
                    int slot = b2 * Kk + j;
                    int q = atomicAdd(&g_cnt[slot], 1);
                    g_cs[slot * CAP + q] = p;
                    g_cn[slot * CAP + q] = n;
                    g_cb[slot * CAP + q] = box;
                } else {
                    t[5 + j] = 0.0f;
                }
            }
        } else {
            #pragma unroll
            for (int j = 0; j < Kk; j++) t[5 + j] = 0.0f;
        }
    }
    __syncthreads();

    // ---- Coalesced vectorized store back to out.
    {
        const float4* src = (const float4*)s_data;
        float4* dst = (float4*)(out + (size_t)blockBase * CELL);
        int n4 = cells * CELL / 4;
        for (int i = tid; i < n4; i += TPB) dst[i] = src[i];
    }

    // ---- Done-barrier: last finishing block runs the tiny NMS tail.
    __threadfence();
    __syncthreads();
    if (tid == 0) s_done = atomicAdd(&g_done, 1u);
    __syncthreads();
    if (s_done != (unsigned)(NBLK - 1)) return;

    if (tid == 0) g_done = 0;          // reset for next graph replay
    __threadfence();

    // ---- NMS tail (last block only): greedy per-(b,k) over compacted lists.
    for (int t = tid; t < NBK; t += TPB) {
        int V = g_cnt[t];
        g_cnt[t] = 0;                  // reset for next replay
        if (V <= 1) continue;

        int b = t / Kk;
        int k = t % Kk;
        const float*  cs = g_cs + (size_t)t * CAP;
        const int*    cn = g_cn + (size_t)t * CAP;
        const float4* cb = g_cb + (size_t)t * CAP;

        unsigned sup[SUPW], used[SUPW];
        int nw = (V + 31) >> 5;
        for (int w = 0; w < nw; w++) { sup[w] = 0u; used[w] = 0u; }

        // Greedy in (score desc, index asc) order — matches stable argsort.
        for (int it = 0; it < V; it++) {
            int   best = -1, bn = 0x7fffffff;
            float bs = -1.0f;
            for (int j = 0; j < V; j++) {
                if ((used[j >> 5] >> (j & 31)) & 1u) continue;
                float sj = cs[j];
                int   nj = cn[j];
                if (sj > bs || (sj == bs && nj < bn)) { best = j; bs = sj; bn = nj; }
            }
            used[best >> 5] |= 1u << (best & 31);
            if ((sup[best >> 5] >> (best & 31)) & 1u) continue;   // not alive

            float4 bb = cb[best];
            float  ab = (bb.z - bb.x) * (bb.w - bb.y);
            for (int j = 0; j < V; j++) {
                if ((used[j >> 5] >> (j & 31)) & 1u) continue;
                if ((sup[j >> 5]  >> (j & 31)) & 1u) continue;
                float4 cj = cb[j];
                float iw = fminf(bb.z, cj.z) - fmaxf(bb.x, cj.x);
                float ih = fminf(bb.w, cj.w) - fmaxf(bb.y, cj.y);
                iw = fmaxf(iw, 0.0f);
                ih = fmaxf(ih, 0.0f);
                float inter = iw * ih;
                float aj    = (cj.z - cj.x) * (cj.w - cj.y);
                float uni   = fmaxf(ab + aj - inter, 1e-9f);
                if (inter / uni > NMS_TH) sup[j >> 5] |= 1u << (j & 31);
            }
        }
        for (int j = 0; j < V; j++) {
            if ((sup[j >> 5] >> (j & 31)) & 1u)
                out[((size_t)(b * Nn + cn[j])) * CELL + 5 + k] = 0.0f;
        }
    }
}

extern "C" void kernel_launch(void* const* d_in, const int* in_sizes, int n_in,
                              void* d_out, int out_size) {
    const float* x    = (const float*)d_in[0];
    const float* bias = (const float*)d_in[1];
    float* out        = (float*)d_out;
    region_fused<<<NBLK, TPB>>>(x, bias, out);
}